// round 7
// baseline (speedup 1.0000x reference)
#include <cuda_runtime.h>
#include <cstdint>

// Fixed problem shape.
#define BB 8
#define QQ 900
#define KK 1203
#define NN 100
#define ROW_BYTES (KK * 4)            // 4812
#define RPW 4                         // rows per warp; 4 | 900 -> same batch
#define SPAN_BYTES (RPW * ROW_BYTES)  // 19248
#define BUF_FLOATS 4816               // 19264 B: span + 16B align slack
#define WARPS 2
#define THREADS (WARPS * 32)
#define BLOCKS (BB * QQ / (RPW * WARPS))   // 900

__device__ __forceinline__ uint32_t smem_u32(const void* p) {
    uint32_t a;
    asm("{ .reg .u64 t; cvta.to.shared.u64 t, %1; cvt.u32.u64 %0, t; }" : "=r"(a) : "l"(p));
    return a;
}

__global__ void __launch_bounds__(THREADS) matcher_cost_kernel(
    const float*  __restrict__ logits,   // (B,Q,K)
    const float4* __restrict__ pboxes,   // (B,Q,4)
    const int*    __restrict__ labels,   // (B,N)
    const float4* __restrict__ tboxes,   // (B,N,4)
    float* __restrict__ out)             // (B,Q,N)
{
    __shared__ float s_buf[WARPS][BUF_FLOATS];            // 38,528 B
    __shared__ alignas(8) unsigned long long s_mbar[WARPS];

    const int tid  = threadIdx.x;
    const int w    = tid >> 5;
    const int lane = tid & 31;

    if (tid < WARPS)
        asm volatile("mbarrier.init.shared.b64 [%0], 1;"
                     :: "r"(smem_u32(&s_mbar[tid])) : "memory");
    asm volatile("fence.proxy.async.shared::cta;" ::: "memory");
    __syncthreads();

    const long row0  = ((long)blockIdx.x * WARPS + w) * RPW;
    const long base  = row0 * ROW_BYTES;
    const long abase = base & ~15L;
    const int  head4 = (int)(base & 15L) >> 2;           // float offset of row0

    const uint32_t mb = smem_u32(&s_mbar[w]);
    const uint32_t sb = smem_u32(&s_buf[w][0]);

    // ---- ONE bulk copy per warp: 4 contiguous rows, all traffic upfront ----
    if (lane == 0) {
        const int size = (SPAN_BYTES + (int)(base & 15L) + 15) & ~15;   // <= 19264
        asm volatile("mbarrier.arrive.expect_tx.shared.b64 _, [%0], %1;"
                     :: "r"(mb), "r"(size) : "memory");
        asm volatile("cp.async.bulk.shared::cta.global.mbarrier::complete_tx::bytes "
                     "[%0], [%1], %2, [%3];"
                     :: "r"(sb), "l"((const char*)logits + abase), "r"(size), "r"(mb)
                     : "memory");
    }

    // ---- warp-invariant target data (L1/L2-hot tiny arrays), hoisted ----
    const int b   = (int)(row0 / QQ);
    const int bn0 = b * NN;
    int    labv[4];
    float4 tbv[4];
    #pragma unroll
    for (int i = 0; i < 4; i++) {
        int n = lane + i * 32;
        int nn = min(n, NN - 1);                 // safe dummy for masked lanes
        labv[i] = min(max(__ldg(labels + bn0 + nn), 0), KK - 1);
        tbv[i]  = __ldg(tboxes + bn0 + nn);
    }

    // ---- wait once for the whole 4-row span ----
    {
        uint32_t done;
        asm volatile(
            "{\n\t.reg .pred p;\n\t"
            "mbarrier.try_wait.parity.acquire.cta.shared::cta.b64 p, [%1], 0;\n\t"
            "selp.b32 %0, 1, 0, p;\n\t}"
            : "=r"(done) : "r"(mb) : "memory");
        if (!done) {
            asm volatile(
                "{\n\t.reg .pred P1;\n\t"
                "W%=:\n\t"
                "mbarrier.try_wait.parity.acquire.cta.shared::cta.b64 P1, [%0], 0, 0x989680;\n\t"
                "@P1 bra.uni D%=;\n\t"
                "bra.uni W%=;\n\t"
                "D%=:\n\t}"
                :: "r"(mb) : "memory");
        }
    }

    // ---- compute 4 rows from SMEM ----
    #pragma unroll 1
    for (int r = 0; r < RPW; r++) {
        const long row = row0 + r;
        const float* rdata = s_buf[w] + head4 + r * KK;

        const float4 pb = pboxes[row];
        const float px0 = pb.x - 0.5f * pb.z, px1 = pb.x + 0.5f * pb.z;
        const float py0 = pb.y - 0.5f * pb.w, py1 = pb.y + 0.5f * pb.w;
        const float area1 = pb.z * pb.w;
        float* const orow = out + row * NN;

        #pragma unroll
        for (int i = 0; i < 4; i++) {
            int n = lane + i * 32;
            if (n < NN) {
                float x = rdata[labv[i]];          // LDS select

                // focal class cost (3 MUFU)
                float e  = __expf(-x);
                float sg = 1.0f + e;
                float p  = __fdividef(1.0f, sg);
                float L  = __logf(sg);
                float logp   = fmaxf(-L,     -18.420681f);
                float log1mp = fmaxf(-x - L, -18.420681f);
                float omp = 1.0f - p;
                float cls = -0.25f * omp * omp * logp + 0.75f * p * p * log1mp;

                // L1 box cost
                float4 tb = tbv[i];
                float l1 = fabsf(pb.x - tb.x) + fabsf(pb.y - tb.y)
                         + fabsf(pb.z - tb.z) + fabsf(pb.w - tb.w);

                // GIoU (1 MUFU)
                float tx0 = tb.x - 0.5f * tb.z, tx1 = tb.x + 0.5f * tb.z;
                float ty0 = tb.y - 0.5f * tb.w, ty1 = tb.y + 0.5f * tb.w;
                float area2 = tb.z * tb.w;
                float wi = fmaxf(fminf(px1, tx1) - fmaxf(px0, tx0), 0.0f);
                float hi = fmaxf(fminf(py1, ty1) - fmaxf(py0, ty0), 0.0f);
                float inter = wi * hi;
                float uni   = area1 + area2 - inter;
                float wc = fmaxf(px1, tx1) - fminf(px0, tx0);
                float hc = fmaxf(py1, ty1) - fminf(py0, ty0);
                float ac = wc * hc;
                float num  = ac * (inter - uni) + uni * uni;
                float giou = num * __fdividef(1.0f, uni * ac);

                orow[n] = 2.0f * cls + 5.0f * l1 - 2.0f * giou;
            }
        }
    }
}

extern "C" void kernel_launch(void* const* d_in, const int* in_sizes, int n_in,
                              void* d_out, int out_size)
{
    const float*  logits = (const float*)d_in[0];
    const float4* pboxes = (const float4*)d_in[1];
    const int*    labels = (const int*)d_in[2];
    const float4* tboxes = (const float4*)d_in[3];
    float* out = (float*)d_out;

    matcher_cost_kernel<<<BLOCKS, THREADS>>>(logits, pboxes, labels, tboxes, out);
}

// round 8
// speedup vs baseline: 1.2353x; 1.2353x over previous
#include <cuda_runtime.h>
#include <cstdint>

// Fixed problem shape.
#define BB 8
#define QQ 900
#define KK 1203
#define NN 100
#define ROW_BYTES (KK * 4)        // 4812
#define BUF_FLOATS 1216           // 4864 B per row buffer (head slack incl.)
#define WARPS 8
#define THREADS (WARPS * 32)      // 256
#define RPW 2                     // rows per warp; 2 | 900 -> pair never straddles batch
#define BLOCKS (BB * QQ / (WARPS * RPW))   // 450
#define DYN_SMEM (WARPS * RPW * BUF_FLOATS * 4)  // 77824 B

__device__ __forceinline__ uint32_t smem_u32(const void* p) {
    uint32_t a;
    asm("{ .reg .u64 t; cvta.to.shared.u64 t, %1; cvt.u32.u64 %0, t; }" : "=r"(a) : "l"(p));
    return a;
}

__device__ __forceinline__ void issue_row_copy(uint32_t sbuf, const char* gbase,
                                               long row, uint32_t mbar) {
    long base    = row * (long)ROW_BYTES;
    long aligned = base & ~15L;
    int  size    = (ROW_BYTES + (int)(base & 15L) + 15) & ~15;   // <= 4832
    asm volatile("mbarrier.arrive.expect_tx.shared.b64 _, [%0], %1;"
                 :: "r"(mbar), "r"(size) : "memory");
    asm volatile("cp.async.bulk.shared::cta.global.mbarrier::complete_tx::bytes "
                 "[%0], [%1], %2, [%3];"
                 :: "r"(sbuf), "l"(gbase + aligned), "r"(size), "r"(mbar) : "memory");
}

__device__ __forceinline__ void mbar_wait0(uint32_t mbar) {
    uint32_t done;
    asm volatile(
        "{\n\t.reg .pred p;\n\t"
        "mbarrier.try_wait.parity.acquire.cta.shared::cta.b64 p, [%1], 0;\n\t"
        "selp.b32 %0, 1, 0, p;\n\t}"
        : "=r"(done) : "r"(mbar) : "memory");
    if (!done) {
        asm volatile(
            "{\n\t.reg .pred P1;\n\t"
            "W%=:\n\t"
            "mbarrier.try_wait.parity.acquire.cta.shared::cta.b64 P1, [%0], 0, 0x989680;\n\t"
            "@P1 bra.uni D%=;\n\t"
            "bra.uni W%=;\n\t"
            "D%=:\n\t}"
            :: "r"(mbar) : "memory");
    }
}

__global__ void __launch_bounds__(THREADS, 2) matcher_cost_kernel(
    const float*  __restrict__ logits,   // (B,Q,K)
    const float4* __restrict__ pboxes,   // (B,Q,4)
    const int*    __restrict__ labels,   // (B,N)
    const float4* __restrict__ tboxes,   // (B,N,4)
    float* __restrict__ out)             // (B,Q,N)
{
    extern __shared__ float s_dyn[];                       // WARPS*2 row buffers
    __shared__ alignas(8) unsigned long long s_mbar[WARPS][2];

    const int tid  = threadIdx.x;
    const int w    = tid >> 5;
    const int lane = tid & 31;

    if (tid < WARPS * 2)
        asm volatile("mbarrier.init.shared.b64 [%0], 1;"
                     :: "r"(smem_u32(&s_mbar[tid >> 1][tid & 1])) : "memory");
    asm volatile("fence.proxy.async.shared::cta;" ::: "memory");
    __syncthreads();

    const long g    = (long)blockIdx.x * WARPS + w;
    const long row0 = g * RPW;                       // rows row0, row0+1 (same batch)
    const char* gbase = (const char*)logits;

    float* const buf0 = s_dyn + (w * 2 + 0) * BUF_FLOATS;
    float* const buf1 = s_dyn + (w * 2 + 1) * BUF_FLOATS;
    const uint32_t mb0 = smem_u32(&s_mbar[w][0]);
    const uint32_t mb1 = smem_u32(&s_mbar[w][1]);

    // ---- both row copies in flight immediately ----
    if (lane == 0) {
        issue_row_copy(smem_u32(buf0), gbase, row0,     mb0);
        issue_row_copy(smem_u32(buf1), gbase, row0 + 1, mb1);
    }

    // ---- warp-invariant target data while copies fly ----
    const int b   = (int)(row0 / QQ);
    const int bn0 = b * NN;
    int    labv[4];
    float4 tbv[4];
    #pragma unroll
    for (int i = 0; i < 4; i++) {
        int n  = lane + i * 32;
        int nn = min(n, NN - 1);
        labv[i] = min(max(__ldg(labels + bn0 + nn), 0), KK - 1);
        tbv[i]  = __ldg(tboxes + bn0 + nn);
    }

    #pragma unroll
    for (int r = 0; r < RPW; r++) {
        const long row = row0 + r;
        mbar_wait0(r ? mb1 : mb0);
        const float* rdata = (r ? buf1 : buf0)
                           + (((int)((row * (long)ROW_BYTES) & 15L)) >> 2);

        const float4 pb = pboxes[row];
        const float px0 = pb.x - 0.5f * pb.z, px1 = pb.x + 0.5f * pb.z;
        const float py0 = pb.y - 0.5f * pb.w, py1 = pb.y + 0.5f * pb.w;
        const float area1 = pb.z * pb.w;
        float* const orow = out + row * NN;

        #pragma unroll
        for (int i = 0; i < 4; i++) {
            int n = lane + i * 32;
            if (n < NN) {
                float x = rdata[labv[i]];          // LDS select

                // focal class cost (3 MUFU)
                float e  = __expf(-x);
                float sg = 1.0f + e;
                float p  = __fdividef(1.0f, sg);
                float L  = __logf(sg);
                float logp   = fmaxf(-L,     -18.420681f);
                float log1mp = fmaxf(-x - L, -18.420681f);
                float omp = 1.0f - p;
                float cls = -0.25f * omp * omp * logp + 0.75f * p * p * log1mp;

                // L1 box cost
                float4 tb = tbv[i];
                float l1 = fabsf(pb.x - tb.x) + fabsf(pb.y - tb.y)
                         + fabsf(pb.z - tb.z) + fabsf(pb.w - tb.w);

                // GIoU (1 MUFU)
                float tx0 = tb.x - 0.5f * tb.z, tx1 = tb.x + 0.5f * tb.z;
                float ty0 = tb.y - 0.5f * tb.w, ty1 = tb.y + 0.5f * tb.w;
                float area2 = tb.z * tb.w;
                float wi = fmaxf(fminf(px1, tx1) - fmaxf(px0, tx0), 0.0f);
                float hi = fmaxf(fminf(py1, ty1) - fmaxf(py0, ty0), 0.0f);
                float inter = wi * hi;
                float uni   = area1 + area2 - inter;
                float wc = fmaxf(px1, tx1) - fminf(px0, tx0);
                float hc = fmaxf(py1, ty1) - fminf(py0, ty0);
                float ac = wc * hc;
                float num  = ac * (inter - uni) + uni * uni;
                float giou = num * __fdividef(1.0f, uni * ac);

                orow[n] = 2.0f * cls + 5.0f * l1 - 2.0f * giou;
            }
        }
    }
}

extern "C" void kernel_launch(void* const* d_in, const int* in_sizes, int n_in,
                              void* d_out, int out_size)
{
    const float*  logits = (const float*)d_in[0];
    const float4* pboxes = (const float4*)d_in[1];
    const int*    labels = (const int*)d_in[2];
    const float4* tboxes = (const float4*)d_in[3];
    float* out = (float*)d_out;

    cudaFuncSetAttribute(matcher_cost_kernel,
                         cudaFuncAttributeMaxDynamicSharedMemorySize, DYN_SMEM);
    matcher_cost_kernel<<<BLOCKS, THREADS, DYN_SMEM>>>(logits, pboxes, labels,
                                                       tboxes, out);
}